// round 6
// baseline (speedup 1.0000x reference)
#include <cuda_runtime.h>
#include <math.h>

#define NB 148      // persistent grid size (<= SM count)
#define NT 256
#define BB 256      // batch
#define HH 512      // hidden = DIN
#define LE 48       // encoder length
#define LOOKN 10    // decoder steps
#define GG 2048     // 4*H
#define KTG 1040    // padded K for tg gates (1 + 512 + 512 = 1025 -> 1040)
#define MM2 (BB*LE) // 12288

// ----------------------------- device scratch -----------------------------
__device__ float g_Wtg[GG * KTG];
__device__ float g_Wsp[GG * 1024];
__device__ float g_Wmid[GG * 1024];
__device__ float g_Wth[1024 * 1024];   // rows 0..511 = Wt_w, 512..1023 = Wh_w
__device__ float g_btg[GG], g_bsp[GG], g_bmid[GG];
__device__ float g_wi[MM2 * HH];       // rows (b*48+l)
__device__ float g_mid[LE * BB * HH];  // [l][b][h]
__device__ float g_mid2[MM2 * HH];     // rows (b*48+l)
__device__ float g_u2v[MM2 * HH];
__device__ float g_ht[2][BB * HH], g_ct[BB * HH];
__device__ float g_he[2][BB * HH], g_ce[BB * HH];
__device__ float g_hm[2][BB * HH], g_cm[BB * HH];
__device__ float g_dec[BB * HH];
__device__ float g_xmod[BB * HH];
__device__ float g_wtwh[BB * 1024];    // cols 0..511 = wt, 512..1023 = wh
__device__ float g_uu[BB * HH];
__device__ float g_score[BB * HH];
__device__ float g_lab[BB];
__device__ float g_sc[MM2];
__device__ unsigned g_bar_cnt;
__device__ unsigned g_bar_gen;

// ----------------------------- grid barrier -----------------------------
__device__ __forceinline__ void gridbar(unsigned &gen) {
    __syncthreads();
    if (threadIdx.x == 0) {
        __threadfence();
        if (atomicAdd(&g_bar_cnt, 1u) == (unsigned)(NB - 1)) {
            g_bar_cnt = 0u;
            __threadfence();
            atomicExch(&g_bar_gen, gen + 1u);
        } else {
            while (*((volatile unsigned*)&g_bar_gen) == gen) __nanosleep(32);
        }
        __threadfence();
    }
    __syncthreads();
    gen++;
}

__device__ __forceinline__ float sigm(float x) { return 1.f / (1.f + expf(-x)); }

// A loader. ASRC 0: plain, ld K. ASRC 1: [A0|A1] concat, each ld 512.
// ASRC 2: tg gather: k==0 -> A0(lab), 1..512 -> A1(dec), 513..1024 -> A2(h), else 0.
template <int ASRC>
__device__ __forceinline__ float4 ldA4(const float* __restrict__ A0,
                                       const float* __restrict__ A1,
                                       const float* __restrict__ A2,
                                       int m, int k, int K) {
    if (ASRC == 0) {
        return *reinterpret_cast<const float4*>(A0 + (size_t)m * K + k);
    } else if (ASRC == 1) {
        const float* p = (k < HH) ? (A0 + ((size_t)m << 9) + k)
                                  : (A1 + ((size_t)m << 9) + (k - HH));
        return *reinterpret_cast<const float4*>(p);
    } else {
        float4 r; float* rp = (float*)&r;
#pragma unroll
        for (int e = 0; e < 4; e++) {
            int kk = k + e; float v;
            if (kk == 0)        v = A0[m];
            else if (kk < 513)  v = A1[((size_t)m << 9) + kk - 1];
            else if (kk < 1025) v = A2[((size_t)m << 9) + kk - 513];
            else                v = 0.f;
            rp[e] = v;
        }
        return r;
    }
}

// ----- 64x64 GEMM tile: C = epi(A @ B^T). 256 threads, 4x4 micro, reg prefetch.
// EPI 0: none. 1: +bias[n]. 2: tanh(v + add1[m*s1+n] + add2[m*1024+n]).
// 3: tanh(v + bias[n] + add2[(m/48)*1024 + 512 + n]).
template <int ASRC, int EPI>
__device__ void gemm64(float* smem, int bm, int bn, int K,
                       const float* __restrict__ A0, const float* __restrict__ A1,
                       const float* __restrict__ Bw, float* __restrict__ C, int ldc,
                       const float* __restrict__ bias,
                       const float* __restrict__ add1, int s1,
                       const float* __restrict__ add2) {
    float* sA = smem;
    float* sB = smem + 1024;
    const int tid = threadIdx.x;
    const int lr = tid >> 2, lk = (tid & 3) << 2;
    const int tx = tid & 15, ty = tid >> 4;
    float acc[4][4] = {};
    float4 ra = ldA4<ASRC>(A0, A1, (const float*)0, bm + lr, lk, K);
    float4 rb = *reinterpret_cast<const float4*>(Bw + (size_t)(bn + lr) * K + lk);
    const int nkt = K >> 4;
    for (int kt = 0; kt < nkt; ++kt) {
        sA[(lk + 0) * 64 + lr] = ra.x; sA[(lk + 1) * 64 + lr] = ra.y;
        sA[(lk + 2) * 64 + lr] = ra.z; sA[(lk + 3) * 64 + lr] = ra.w;
        sB[(lk + 0) * 64 + lr] = rb.x; sB[(lk + 1) * 64 + lr] = rb.y;
        sB[(lk + 2) * 64 + lr] = rb.z; sB[(lk + 3) * 64 + lr] = rb.w;
        __syncthreads();
        if (kt + 1 < nkt) {
            int k0 = (kt + 1) << 4;
            ra = ldA4<ASRC>(A0, A1, (const float*)0, bm + lr, k0 + lk, K);
            rb = *reinterpret_cast<const float4*>(Bw + (size_t)(bn + lr) * K + k0 + lk);
        }
#pragma unroll
        for (int kk = 0; kk < 16; ++kk) {
            float4 af = *reinterpret_cast<const float4*>(sA + kk * 64 + ty * 4);
            float4 bf = *reinterpret_cast<const float4*>(sB + kk * 64 + tx * 4);
            float av[4] = {af.x, af.y, af.z, af.w};
            float bv[4] = {bf.x, bf.y, bf.z, bf.w};
#pragma unroll
            for (int i = 0; i < 4; i++)
#pragma unroll
                for (int j = 0; j < 4; j++)
                    acc[i][j] = fmaf(av[i], bv[j], acc[i][j]);
        }
        __syncthreads();
    }
#pragma unroll
    for (int i = 0; i < 4; i++) {
        int m = bm + ty * 4 + i;
#pragma unroll
        for (int j = 0; j < 4; j++) {
            int n = bn + tx * 4 + j;
            float v = acc[i][j];
            if (EPI == 1) v += bias[n];
            else if (EPI == 2) v = tanhf(v + add1[(size_t)m * s1 + n] + add2[(size_t)m * 1024 + n]);
            else if (EPI == 3) v = tanhf(v + bias[n] + add2[(size_t)(m / 48) * 1024 + 512 + n]);
            C[(size_t)m * ldc + n] = v;
        }
    }
}

// ----- fused quad-gate GEMM + LSTM cell. Tile: 32 rows x 32 j-cols x 4 gates.
// Wp: packed [4H x K] weight (gate g row = g*512 + j). Writes h, c (RMW), opt hcopy.
template <int ASRC>
__device__ void gemmQuad(float* smem, int bm, int bj, int K,
                         const float* __restrict__ A0, const float* __restrict__ A1,
                         const float* __restrict__ A2,
                         const float* __restrict__ Wp, const float* __restrict__ bias,
                         float* __restrict__ h, float* __restrict__ c,
                         float* __restrict__ hcopy, size_t hstride) {
    float* sA = smem;          // 512 floats
    float* sB = smem + 512;    // 2048 floats
    const int tid = threadIdx.x;
    const int tx = tid & 15, ty = tid >> 4;
    const int am = tid >> 2, akq = tid & 3;       // A slot, threads < 128
    const int g0 = tid >> 7, r0 = tid & 127, j0 = r0 >> 2, kq0 = r0 & 3;
    const int si = tid + 256;
    const int g1 = si >> 7, r1 = si & 127, j1 = r1 >> 2, kq1 = r1 & 3;
    float acc[4][2][2] = {};
    float4 ra = make_float4(0.f, 0.f, 0.f, 0.f), rb0, rb1;
    if (tid < 128) ra = ldA4<ASRC>(A0, A1, A2, bm + am, akq * 4, K);
    rb0 = *reinterpret_cast<const float4*>(Wp + (size_t)(g0 * 512 + bj + j0) * K + kq0 * 4);
    rb1 = *reinterpret_cast<const float4*>(Wp + (size_t)(g1 * 512 + bj + j1) * K + kq1 * 4);
    const int nkt = K >> 4;
    for (int kt = 0; kt < nkt; ++kt) {
        if (tid < 128) {
            sA[(akq * 4 + 0) * 32 + am] = ra.x; sA[(akq * 4 + 1) * 32 + am] = ra.y;
            sA[(akq * 4 + 2) * 32 + am] = ra.z; sA[(akq * 4 + 3) * 32 + am] = ra.w;
        }
        sB[g0 * 512 + (kq0 * 4 + 0) * 32 + j0] = rb0.x;
        sB[g0 * 512 + (kq0 * 4 + 1) * 32 + j0] = rb0.y;
        sB[g0 * 512 + (kq0 * 4 + 2) * 32 + j0] = rb0.z;
        sB[g0 * 512 + (kq0 * 4 + 3) * 32 + j0] = rb0.w;
        sB[g1 * 512 + (kq1 * 4 + 0) * 32 + j1] = rb1.x;
        sB[g1 * 512 + (kq1 * 4 + 1) * 32 + j1] = rb1.y;
        sB[g1 * 512 + (kq1 * 4 + 2) * 32 + j1] = rb1.z;
        sB[g1 * 512 + (kq1 * 4 + 3) * 32 + j1] = rb1.w;
        __syncthreads();
        if (kt + 1 < nkt) {
            int k0 = (kt + 1) << 4;
            if (tid < 128) ra = ldA4<ASRC>(A0, A1, A2, bm + am, k0 + akq * 4, K);
            rb0 = *reinterpret_cast<const float4*>(Wp + (size_t)(g0 * 512 + bj + j0) * K + k0 + kq0 * 4);
            rb1 = *reinterpret_cast<const float4*>(Wp + (size_t)(g1 * 512 + bj + j1) * K + k0 + kq1 * 4);
        }
#pragma unroll
        for (int kk = 0; kk < 16; ++kk) {
            float a0 = sA[kk * 32 + ty * 2], a1 = sA[kk * 32 + ty * 2 + 1];
#pragma unroll
            for (int g = 0; g < 4; g++) {
                float b0 = sB[g * 512 + kk * 32 + tx * 2];
                float b1 = sB[g * 512 + kk * 32 + tx * 2 + 1];
                acc[g][0][0] = fmaf(a0, b0, acc[g][0][0]);
                acc[g][0][1] = fmaf(a0, b1, acc[g][0][1]);
                acc[g][1][0] = fmaf(a1, b0, acc[g][1][0]);
                acc[g][1][1] = fmaf(a1, b1, acc[g][1][1]);
            }
        }
        __syncthreads();
    }
#pragma unroll
    for (int i = 0; i < 2; i++) {
        int m = bm + ty * 2 + i;
#pragma unroll
        for (int j = 0; j < 2; j++) {
            int jc = bj + tx * 2 + j;
            float gi = acc[0][i][j] + bias[jc];
            float gf = acc[1][i][j] + bias[512 + jc];
            float gg = acc[2][i][j] + bias[1024 + jc];
            float go = acc[3][i][j] + bias[1536 + jc];
            size_t off = ((size_t)m << 9) + jc;
            float c2 = sigm(gf) * c[off] + sigm(gi) * tanhf(gg);
            float hn = sigm(go) * tanhf(c2);
            c[off] = c2;
            h[off] = hn;
            if (hcopy) hcopy[(size_t)m * hstride + jc] = hn;
        }
    }
}

// ----------------------------- megakernel -----------------------------
__global__ void __launch_bounds__(NT, 1)
mega(const float* __restrict__ input, const float* __restrict__ label_p,
     const float* __restrict__ Wih_sp, const float* __restrict__ Whh_sp,
     const float* __restrict__ bih_sp, const float* __restrict__ bhh_sp,
     const float* __restrict__ Wih_tg, const float* __restrict__ Whh_tg,
     const float* __restrict__ bih_tg, const float* __restrict__ bhh_tg,
     const float* __restrict__ Wih_mid, const float* __restrict__ Whh_mid,
     const float* __restrict__ bih_mid, const float* __restrict__ bhh_mid,
     const float* __restrict__ Wi_w, const float* __restrict__ Wi_b,
     const float* __restrict__ We_w, const float* __restrict__ Wt_w,
     const float* __restrict__ Vd_w, const float* __restrict__ Vd_b,
     const float* __restrict__ Wx_w, const float* __restrict__ Wx_b,
     const float* __restrict__ Wh_w, const float* __restrict__ V_w,
     const float* __restrict__ V_b, const float* __restrict__ reg_w,
     const float* __restrict__ reg_b, float* __restrict__ out) {
    extern __shared__ float smem[];
    unsigned gen = *((volatile unsigned*)&g_bar_gen);  // read before any arrival
    const int tid = threadIdx.x;
    const int gtid = blockIdx.x * NT + tid;
    const int gstride = NB * NT;

    // ---- S0: pack weights, biases, init state ----
    for (int i = gtid; i < GG * KTG; i += gstride) {
        int r = i / KTG, cc = i - r * KTG;
        float v = 0.f;
        if (cc < 513)       v = Wih_tg[r * 513 + cc];
        else if (cc < 1025) v = Whh_tg[(r << 9) + cc - 513];
        g_Wtg[i] = v;
    }
    for (int i = gtid; i < GG * 1024; i += gstride) {
        int r = i >> 10, cc = i & 1023;
        g_Wsp[i]  = cc < 512 ? Wih_sp[(r << 9) + cc]  : Whh_sp[(r << 9) + cc - 512];
        g_Wmid[i] = cc < 512 ? Wih_mid[(r << 9) + cc] : Whh_mid[(r << 9) + cc - 512];
    }
    for (int i = gtid; i < 1024 * 1024; i += gstride) {
        int r = i >> 10, cc = i & 1023;
        g_Wth[i] = r < 512 ? Wt_w[(r << 10) + cc] : Wh_w[((r - 512) << 10) + cc];
    }
    for (int i = gtid; i < GG; i += gstride) {
        g_btg[i] = bih_tg[i] + bhh_tg[i];
        g_bsp[i] = bih_sp[i] + bhh_sp[i];
        g_bmid[i] = bih_mid[i] + bhh_mid[i];
    }
    for (int i = gtid; i < BB * HH; i += gstride) { g_ht[0][i] = 0.f; g_ct[i] = 0.f; g_dec[i] = 0.f; }
    for (int i = gtid; i < BB; i += gstride) g_lab[i] = label_p[i * (LE + LOOKN) + LE]; // START=48
    gridbar(gen);

    // ---- S1: wi = input @ Wi^T + Wi_b  (12288 x 512 x 512) ----
    for (int tile = blockIdx.x; tile < 1536; tile += NB) {
        int tm = tile >> 3, tn = tile & 7;
        gemm64<0, 1>(smem, tm * 64, tn * 64, 512, input, 0, Wi_w, g_wi, 512, Wi_b, 0, 0, 0);
    }
    gridbar(gen);

#pragma unroll 1
    for (int t = 0; t < LOOKN; t++) {
        const float* htO = g_ht[t & 1];
        float* htN = g_ht[(t & 1) ^ 1];
        // P1: tg gates (gather A) + LSTM -> htN, ct
        for (int tile = blockIdx.x; tile < 128; tile += NB) {
            int tm = tile >> 4, tj = tile & 15;
            gemmQuad<2>(smem, tm * 32, tj * 32, KTG, g_lab, g_dec, htO,
                        g_Wtg, g_btg, htN, g_ct, (float*)0, 0);
        }
        gridbar(gen);
        // P2: wtwh = [htN|ct] @ Wth^T  +  rowdot(target/lab/out)  +  zero inner states
        for (int tile = blockIdx.x; tile < 64; tile += NB) {
            int tm = tile >> 4, tn = tile & 15;
            gemm64<1, 0>(smem, tm * 64, tn * 64, 1024, htN, g_ct, g_Wth, g_wtwh, 1024, 0, 0, 0, 0);
        }
        for (int u = blockIdx.x; u < 32; u += NB) {
            int row = u * 8 + (tid >> 5), lane = tid & 31;
            const float* x = htN + ((size_t)row << 9);
            float s = 0.f;
#pragma unroll
            for (int k = lane * 4; k < 512; k += 128) {
                float4 xv = *(const float4*)(x + k);
                float4 wv = *(const float4*)(reg_w + k);
                s = fmaf(xv.x, wv.x, s); s = fmaf(xv.y, wv.y, s);
                s = fmaf(xv.z, wv.z, s); s = fmaf(xv.w, wv.w, s);
            }
#pragma unroll
            for (int o = 16; o; o >>= 1) s += __shfl_xor_sync(0xffffffffu, s, o);
            if (lane == 0) { s += reg_b[0]; out[row * LOOKN + t] = s; g_lab[row] = s; }
        }
        for (int i = gtid; i < BB * HH; i += gstride) {
            g_he[0][i] = 0.f; g_ce[i] = 0.f; g_hm[0][i] = 0.f; g_cm[i] = 0.f;
        }
        gridbar(gen);

        // ---- sp attention loop ----
#pragma unroll 1
        for (int l = 0; l < LE; l++) {
            const float* heO = g_he[l & 1];
            float* heN = g_he[(l & 1) ^ 1];
            // P3: u = tanh([heO|ce] @ We^T + wi[:,l,:] + wt)
            for (int tile = blockIdx.x; tile < 32; tile += NB) {
                int tm = tile >> 3, tn = tile & 7;
                gemm64<1, 2>(smem, tm * 64, tn * 64, 1024, heO, g_ce, We_w, g_uu, 512,
                             0, g_wi + l * 512, LE * HH, g_wtwh);
            }
            gridbar(gen);
            // P4: score = u @ Vd^T + Vd_b
            for (int tile = blockIdx.x; tile < 32; tile += NB) {
                int tm = tile >> 3, tn = tile & 7;
                gemm64<0, 1>(smem, tm * 64, tn * 64, 512, g_uu, 0, Vd_w, g_score, 512,
                             Vd_b, 0, 0, 0);
            }
            gridbar(gen);
            // P5: xmod = x * softmax(score)
            for (int r = blockIdx.x; r < BB; r += NB) {
                __syncthreads();
                float v0 = g_score[(r << 9) + tid], v1 = g_score[(r << 9) + tid + 256];
                float mx = fmaxf(v0, v1);
#pragma unroll
                for (int o = 16; o; o >>= 1) mx = fmaxf(mx, __shfl_xor_sync(0xffffffffu, mx, o));
                if ((tid & 31) == 0) smem[tid >> 5] = mx;
                __syncthreads();
                float M = smem[0];
#pragma unroll
                for (int i = 1; i < 8; i++) M = fmaxf(M, smem[i]);
                float e0 = expf(v0 - M), e1 = expf(v1 - M);
                float sm = e0 + e1;
#pragma unroll
                for (int o = 16; o; o >>= 1) sm += __shfl_xor_sync(0xffffffffu, sm, o);
                __syncthreads();
                if ((tid & 31) == 0) smem[tid >> 5] = sm;
                __syncthreads();
                float S = 0.f;
#pragma unroll
                for (int i = 0; i < 8; i++) S += smem[i];
                float inv = 1.f / S;
                const float* xr = input + ((size_t)r * LE + l) * 512;
                g_xmod[(r << 9) + tid]       = xr[tid] * e0 * inv;
                g_xmod[(r << 9) + tid + 256] = xr[tid + 256] * e1 * inv;
            }
            gridbar(gen);
            // P6: sp gates ([xmod|heO]) + LSTM -> heN, ce, mid[l]
            for (int tile = blockIdx.x; tile < 128; tile += NB) {
                int tm = tile >> 4, tj = tile & 15;
                gemmQuad<1>(smem, tm * 32, tj * 32, 1024, g_xmod, heO, (const float*)0,
                            g_Wsp, g_bsp, heN, g_ce, g_mid + (size_t)l * BB * HH, 512);
            }
            gridbar(gen);
        }

        // ---- mid LSTM loop ----
#pragma unroll 1
        for (int l = 0; l < LE; l++) {
            const float* hmO = g_hm[l & 1];
            float* hmN = g_hm[(l & 1) ^ 1];
            for (int tile = blockIdx.x; tile < 128; tile += NB) {
                int tm = tile >> 4, tj = tile & 15;
                gemmQuad<1>(smem, tm * 32, tj * 32, 1024, g_mid + (size_t)l * BB * HH, hmO,
                            (const float*)0, g_Wmid, g_bmid, hmN, g_cm,
                            g_mid2 + (size_t)l * 512, (size_t)LE * HH);
            }
            gridbar(gen);
        }

        // P8: u2 = tanh(mid2 @ Wx^T + Wx_b + wh[b])  (12288 x 512 x 512)
        for (int tile = blockIdx.x; tile < 1536; tile += NB) {
            int tm = tile >> 3, tn = tile & 7;
            gemm64<0, 3>(smem, tm * 64, tn * 64, 512, g_mid2, 0, Wx_w, g_u2v, 512,
                         Wx_b, 0, 0, g_wtwh);
        }
        gridbar(gen);
        // P9: sc = u2 @ V_w + V_b
        for (int u = blockIdx.x; u < MM2 / 8; u += NB) {
            int row = u * 8 + (tid >> 5), lane = tid & 31;
            const float* x = g_u2v + ((size_t)row << 9);
            float s = 0.f;
#pragma unroll
            for (int k = lane * 4; k < 512; k += 128) {
                float4 xv = *(const float4*)(x + k);
                float4 wv = *(const float4*)(V_w + k);
                s = fmaf(xv.x, wv.x, s); s = fmaf(xv.y, wv.y, s);
                s = fmaf(xv.z, wv.z, s); s = fmaf(xv.w, wv.w, s);
            }
#pragma unroll
            for (int o = 16; o; o >>= 1) s += __shfl_xor_sync(0xffffffffu, s, o);
            if (lane == 0) g_sc[row] = s + V_b[0];
        }
        gridbar(gen);
        // P10: dec_in[b,h] = sum_l sc[b,l] * mid2[b,l,h]
        for (int b = blockIdx.x; b < BB; b += NB) {
            __syncthreads();
            if (tid < LE) smem[tid] = g_sc[b * LE + tid];
            __syncthreads();
            for (int h2 = tid; h2 < 512; h2 += NT) {
                float s = 0.f;
                const float* m2 = g_mid2 + (size_t)b * LE * HH + h2;
#pragma unroll 8
                for (int ll = 0; ll < LE; ll++) s = fmaf(smem[ll], m2[(size_t)ll * HH], s);
                g_dec[(b << 9) + h2] = s;
            }
        }
        gridbar(gen);
    }
}

// ----------------------------- launch -----------------------------
extern "C" void kernel_launch(void* const* d_in, const int* in_sizes, int n_in,
                              void* d_out, int out_size) {
    mega<<<NB, NT, 3072 * sizeof(float)>>>(
        (const float*)d_in[0],  (const float*)d_in[1],  (const float*)d_in[2],
        (const float*)d_in[3],  (const float*)d_in[4],  (const float*)d_in[5],
        (const float*)d_in[6],  (const float*)d_in[7],  (const float*)d_in[8],
        (const float*)d_in[9],  (const float*)d_in[10], (const float*)d_in[11],
        (const float*)d_in[12], (const float*)d_in[13], (const float*)d_in[14],
        (const float*)d_in[15], (const float*)d_in[16], (const float*)d_in[17],
        (const float*)d_in[18], (const float*)d_in[19], (const float*)d_in[20],
        (const float*)d_in[21], (const float*)d_in[22], (const float*)d_in[23],
        (const float*)d_in[24], (const float*)d_in[25], (const float*)d_in[26],
        (float*)d_out);
}

// round 7
// speedup vs baseline: 1.5149x; 1.5149x over previous
#include <cuda_runtime.h>
#include <cuda_bf16.h>
#include <math.h>
typedef __nv_bfloat16 bf;
#define NB 148
#define NT 256
#define LOOKN 10
#define LE 48
#define MM2 12288
#define KTG 1088

// ---------------- device scratch ----------------
__device__ bf g_WtgH[2048*KTG], g_WtgL[2048*KTG];
__device__ bf g_WspH[2048*1024], g_WspL[2048*1024];
__device__ bf g_WmidH[2048*1024], g_WmidL[2048*1024];
__device__ bf g_WthH[1024*1024], g_WthL[1024*1024];
__device__ bf g_WeH[512*1024], g_WeL[512*1024];
__device__ bf g_VdH[512*512], g_VdL[512*512];
__device__ bf g_WxH[512*512], g_WxL[512*512];
__device__ bf g_WiH[512*512], g_WiL[512*512];
__device__ bf g_InH[MM2*512], g_InL[MM2*512];
__device__ bf g_AtgH[256*KTG], g_AtgL[256*KTG];
__device__ bf g_HtH[256*512], g_HtL[256*512];
__device__ bf g_CtH[256*512], g_CtL[256*512];
__device__ bf g_HeH[2][256*512], g_HeL[2][256*512];
__device__ bf g_CeH[256*512], g_CeL[256*512];
__device__ bf g_HmH[2][256*512], g_HmL[2][256*512];
__device__ bf g_XmH[256*512], g_XmL[256*512];
__device__ bf g_UH[256*512], g_UL[256*512];
__device__ bf g_MidH[LE*256*512], g_MidL[LE*256*512];
__device__ bf g_M2H[MM2*512], g_M2L[MM2*512];
__device__ float g_bt[2048], g_bs[2048], g_bm[2048];
__device__ float g_wi[MM2*512], g_mid2[MM2*512], g_u2[MM2*512];
__device__ float g_ht[256*512], g_ct[256*512], g_ce[256*512], g_cm[256*512];
__device__ float g_dec[256*512], g_wtwh[256*1024], g_score[256*512];
__device__ float g_lab[256], g_sc[MM2];
__device__ unsigned g_bc, g_bg;

__device__ __forceinline__ void gridbar(unsigned &gen) {
    __syncthreads();
    if (threadIdx.x == 0) {
        __threadfence();
        if (atomicAdd(&g_bc, 1u) == (unsigned)(NB - 1)) {
            g_bc = 0u; __threadfence();
            atomicExch(&g_bg, gen + 1u);
        } else {
            while (*((volatile unsigned*)&g_bg) == gen) __nanosleep(32);
        }
        __threadfence();
    }
    __syncthreads();
    gen++;
}
__device__ __forceinline__ float sigm(float x) { return 1.f / (1.f + expf(-x)); }
__device__ __forceinline__ void bsplit(float x, bf &h, bf &l) {
    h = __float2bfloat16(x);
    l = __float2bfloat16(x - __bfloat162float(h));
}
__device__ __forceinline__ unsigned su32(const void* p) {
    return (unsigned)__cvta_generic_to_shared(p);
}
__device__ __forceinline__ void ldsm4(unsigned a, unsigned* r) {
    asm volatile("ldmatrix.sync.aligned.m8n8.x4.shared.b16 {%0,%1,%2,%3}, [%4];"
                 : "=r"(r[0]), "=r"(r[1]), "=r"(r[2]), "=r"(r[3]) : "r"(a));
}
__device__ __forceinline__ void mma16816(float* d, const unsigned* a, const unsigned* b) {
    asm volatile("mma.sync.aligned.m16n8k16.row.col.f32.bf16.bf16.f32 "
                 "{%0,%1,%2,%3}, {%4,%5,%6,%7}, {%8,%9}, {%0,%1,%2,%3};"
                 : "+f"(d[0]), "+f"(d[1]), "+f"(d[2]), "+f"(d[3])
                 : "r"(a[0]), "r"(a[1]), "r"(a[2]), "r"(a[3]), "r"(b[0]), "r"(b[1]));
}

// -------- TC tile engine: 32(m) x 64(n), 8 warps, split-bf16 3-pass --------
// CAT2=1: A = [seg0|seg1], each [..][512]. CAT2=0: A plain, ld = K.
template <int CAT2>
__device__ void tc_tile(float acc[][4], int bm, int bn, int K,
                        const bf* __restrict__ A0h, const bf* __restrict__ A0l,
                        const bf* __restrict__ A1h, const bf* __restrict__ A1l,
                        const bf* __restrict__ Bh, const bf* __restrict__ Bl, char* sm) {
    const int tid = threadIdx.x, lane = tid & 31, w = tid >> 5;
    char* sA = sm;              // [2][32][64] bf16, pitch 144B
    char* sB = sm + 9216;       // [2][64][64] bf16, pitch 144B
#pragma unroll
    for (int nf = 0; nf < 2; nf++)
#pragma unroll
        for (int k = 0; k < 4; k++) acc[nf][k] = 0.f;
    const unsigned aA = su32(sA) + ((w & 1) * 16 + (lane & 15)) * 144 + (lane >> 4) * 16;
    const unsigned aB = su32(sB) + ((w >> 1) * 16 + ((lane >> 4) << 3) + (lane & 7)) * 144
                      + ((lane >> 3) & 1) * 16;
    const int ns = K >> 6;
    for (int st = 0; st < ns; st++) {
        const int k0 = st << 6;
        __syncthreads();
#pragma unroll
        for (int c = tid; c < 512; c += NT) {
            int p = c >> 8, row = (c >> 3) & 31, kq = (c & 7) << 3;
            int gk = k0 + kq;
            const bf* src;
            if (CAT2) src = (gk < 512) ? ((p ? A0l : A0h) + (size_t)(bm + row) * 512 + gk)
                                       : ((p ? A1l : A1h) + (size_t)(bm + row) * 512 + gk - 512);
            else      src = (p ? A0l : A0h) + (size_t)(bm + row) * K + gk;
            *(uint4*)(sA + (p * 32 + row) * 144 + kq * 2) = *(const uint4*)src;
        }
#pragma unroll
        for (int c = tid; c < 1024; c += NT) {
            int p = c >> 9, row = (c >> 3) & 63, kq = (c & 7) << 3;
            const bf* src = (p ? Bl : Bh) + (size_t)(bn + row) * K + k0 + kq;
            *(uint4*)(sB + (p * 64 + row) * 144 + kq * 2) = *(const uint4*)src;
        }
        __syncthreads();
#pragma unroll
        for (int kk = 0; kk < 4; kk++) {
            unsigned aH[4], aL[4], bH[4], bL[4];
            ldsm4(aA + kk * 32, aH);
            ldsm4(aA + 32 * 144 + kk * 32, aL);
            ldsm4(aB + kk * 32, bH);
            ldsm4(aB + 64 * 144 + kk * 32, bL);
#pragma unroll
            for (int nf = 0; nf < 2; nf++) {
                mma16816(acc[nf], aH, bH + 2 * nf);
                mma16816(acc[nf], aH, bL + 2 * nf);
                mma16816(acc[nf], aL, bH + 2 * nf);
            }
        }
    }
    __syncthreads();
}

// ---------------- epilogues ----------------
__device__ void epi_store(float acc[][4], int bm, int bn, float* C, int ldc,
                          const float* bias) {
    int lane = threadIdx.x & 31, w = threadIdx.x >> 5;
    int wm = (w & 1) * 16, wn = (w >> 1) * 16;
#pragma unroll
    for (int nf = 0; nf < 2; nf++)
#pragma unroll
        for (int k = 0; k < 4; k++) {
            int m = bm + wm + (lane >> 2) + (k >> 1) * 8;
            int nc = bn + wn + nf * 8 + (lane & 3) * 2 + (k & 1);
            float v = acc[nf][k];
            if (bias) v += bias[nc];
            C[(size_t)m * ldc + nc] = v;
        }
}
__device__ void epi_u(float acc[][4], int bm, int bn, int l) {
    int lane = threadIdx.x & 31, w = threadIdx.x >> 5;
    int wm = (w & 1) * 16, wn = (w >> 1) * 16;
#pragma unroll
    for (int nf = 0; nf < 2; nf++)
#pragma unroll
        for (int k = 0; k < 4; k++) {
            int m = bm + wm + (lane >> 2) + (k >> 1) * 8;
            int nc = bn + wn + nf * 8 + (lane & 3) * 2 + (k & 1);
            float v = tanhf(acc[nf][k] + g_wi[((size_t)m * 48 + l) * 512 + nc]
                            + g_wtwh[(size_t)m * 1024 + nc]);
            size_t ix = ((size_t)m << 9) + nc;
            bsplit(v, g_UH[ix], g_UL[ix]);
        }
}
__device__ void epi_u2(float acc[][4], int bm, int bn, const float* wxb) {
    int lane = threadIdx.x & 31, w = threadIdx.x >> 5;
    int wm = (w & 1) * 16, wn = (w >> 1) * 16;
#pragma unroll
    for (int nf = 0; nf < 2; nf++)
#pragma unroll
        for (int k = 0; k < 4; k++) {
            int m = bm + wm + (lane >> 2) + (k >> 1) * 8;
            int nc = bn + wn + nf * 8 + (lane & 3) * 2 + (k & 1);
            float v = tanhf(acc[nf][k] + wxb[nc] + g_wtwh[(size_t)(m / 48) * 1024 + 512 + nc]);
            g_u2[(size_t)m * 512 + nc] = v;
        }
}
// interleaved-gate LSTM epilogue (B rows packed n' = j*4 + gate)
__device__ void epi_lstm(float acc[][4], int bm, int bn, const float* bias,
                         float* cP, float* hF, bf* hH, bf* hL, bf* cH, bf* cL,
                         float* eF, bf* eH, bf* eL, size_t eOff, int eStr) {
    int lane = threadIdx.x & 31, w = threadIdx.x >> 5;
    int wm = (w & 1) * 16, wn = (w >> 1) * 16;
    int q = lane & 3;
#pragma unroll
    for (int nf = 0; nf < 2; nf++)
#pragma unroll
        for (int rh = 0; rh < 2; rh++) {
            float va = acc[nf][rh * 2 + 0], vb = acc[nf][rh * 2 + 1];
            float pa = __shfl_xor_sync(0xffffffffu, va, 1);
            float pb = __shfl_xor_sync(0xffffffffu, vb, 1);
            if (!(q & 1)) {
                int m = bm + wm + (lane >> 2) + rh * 8;
                int j = (bn + wn + nf * 8 + q * 2) >> 2;
                float gi = va + bias[j], gf = vb + bias[512 + j];
                float gg = pa + bias[1024 + j], go = pb + bias[1536 + j];
                size_t ix = ((size_t)m << 9) + j;
                float c2 = sigm(gf) * cP[ix] + sigm(gi) * tanhf(gg);
                float hn = sigm(go) * tanhf(c2);
                cP[ix] = c2;
                bf hh, hl; bsplit(hn, hh, hl);
                hH[ix] = hh; hL[ix] = hl;
                if (hF) hF[ix] = hn;
                if (cH) { bf ch, cl; bsplit(c2, ch, cl); cH[ix] = ch; cL[ix] = cl; }
                if (eH) {
                    size_t ex = (size_t)m * eStr + eOff + j;
                    eH[ex] = hh; eL[ex] = hl;
                    if (eF) eF[ex] = hn;
                }
            }
        }
}

#define FOR_T(TM, TN) for (int _t = blockIdx.x; _t < (TM) * (TN); _t += NB) { \
    int bm = (_t / (TN)) * 32, bn = (_t % (TN)) * 64; float acc[2][4];
#define END_T }

// ---------------- megakernel ----------------
__global__ void __launch_bounds__(NT, 1)
mega(const float* __restrict__ input, const float* __restrict__ label_p,
     const float* __restrict__ Wih_sp, const float* __restrict__ Whh_sp,
     const float* __restrict__ bih_sp, const float* __restrict__ bhh_sp,
     const float* __restrict__ Wih_tg, const float* __restrict__ Whh_tg,
     const float* __restrict__ bih_tg, const float* __restrict__ bhh_tg,
     const float* __restrict__ Wih_mid, const float* __restrict__ Whh_mid,
     const float* __restrict__ bih_mid, const float* __restrict__ bhh_mid,
     const float* __restrict__ Wi_w, const float* __restrict__ Wi_b,
     const float* __restrict__ We_w, const float* __restrict__ Wt_w,
     const float* __restrict__ Vd_w, const float* __restrict__ Vd_b,
     const float* __restrict__ Wx_w, const float* __restrict__ Wx_b,
     const float* __restrict__ Wh_w, const float* __restrict__ V_w,
     const float* __restrict__ V_b, const float* __restrict__ reg_w,
     const float* __restrict__ reg_b, float* __restrict__ out) {
    extern __shared__ char sm[];
    float* smf = (float*)sm;
    unsigned gen = *((volatile unsigned*)&g_bg);
    const int tid = threadIdx.x;
    const int gtid = blockIdx.x * NT + tid;
    const int gs = NB * NT;
    const bf z = __float2bfloat16(0.f);

    // ---- S0: split/pack weights, biases, init ----
    for (int i = gtid; i < 2048 * KTG; i += gs) {
        int np = i / KTG, cc = i - np * KTG;
        int r = (np & 3) * 512 + (np >> 2);
        float v = 0.f;
        if (cc < 513)       v = Wih_tg[r * 513 + cc];
        else if (cc < 1025) v = Whh_tg[(r << 9) + cc - 513];
        bsplit(v, g_WtgH[i], g_WtgL[i]);
    }
    for (int i = gtid; i < 2048 * 1024; i += gs) {
        int np = i >> 10, cc = i & 1023;
        int r = (np & 3) * 512 + (np >> 2);
        float vs = cc < 512 ? Wih_sp[(r << 9) + cc] : Whh_sp[(r << 9) + cc - 512];
        float vm = cc < 512 ? Wih_mid[(r << 9) + cc] : Whh_mid[(r << 9) + cc - 512];
        bsplit(vs, g_WspH[i], g_WspL[i]);
        bsplit(vm, g_WmidH[i], g_WmidL[i]);
    }
    for (int i = gtid; i < 1024 * 1024; i += gs) {
        int r = i >> 10, cc = i & 1023;
        float v = r < 512 ? Wt_w[(r << 10) + cc] : Wh_w[((r - 512) << 10) + cc];
        bsplit(v, g_WthH[i], g_WthL[i]);
    }
    for (int i = gtid; i < 512 * 1024; i += gs) bsplit(We_w[i], g_WeH[i], g_WeL[i]);
    for (int i = gtid; i < 512 * 512; i += gs) {
        bsplit(Vd_w[i], g_VdH[i], g_VdL[i]);
        bsplit(Wx_w[i], g_WxH[i], g_WxL[i]);
        bsplit(Wi_w[i], g_WiH[i], g_WiL[i]);
    }
    for (int i = gtid; i < MM2 * 512; i += gs) bsplit(input[i], g_InH[i], g_InL[i]);
    for (int i = gtid; i < 2048; i += gs) {
        g_bt[i] = bih_tg[i] + bhh_tg[i];
        g_bs[i] = bih_sp[i] + bhh_sp[i];
        g_bm[i] = bih_mid[i] + bhh_mid[i];
    }
    for (int i = gtid; i < 256 * 512; i += gs) { g_ht[i] = 0.f; g_ct[i] = 0.f; g_dec[i] = 0.f; }
    for (int i = gtid; i < 256; i += gs) g_lab[i] = label_p[i * (LE + LOOKN) + LE];
    gridbar(gen);

    // ---- S1: wi = input @ Wi^T + Wi_b ----
    FOR_T(384, 8)
        tc_tile<0>(acc, bm, bn, 512, g_InH, g_InL, 0, 0, g_WiH, g_WiL, sm);
        epi_store(acc, bm, bn, g_wi, 512, Wi_b);
    END_T
    gridbar(gen);

#pragma unroll 1
    for (int t = 0; t < LOOKN; t++) {
        // PA: pack Atg (split)
        for (int i = gtid; i < 256 * KTG; i += gs) {
            int b = i / KTG, c = i - b * KTG;
            float v = 0.f;
            if (c == 0)        v = g_lab[b];
            else if (c < 513)  v = g_dec[(b << 9) + c - 1];
            else if (c < 1025) v = g_ht[(b << 9) + c - 513];
            bsplit(v, g_AtgH[i], g_AtgL[i]);
        }
        gridbar(gen);
        // P1: tg gates + LSTM
        FOR_T(8, 32)
            tc_tile<0>(acc, bm, bn, KTG, g_AtgH, g_AtgL, 0, 0, g_WtgH, g_WtgL, sm);
            epi_lstm(acc, bm, bn, g_bt, g_ct, g_ht, g_HtH, g_HtL, g_CtH, g_CtL, 0, 0, 0, 0, 0);
        END_T
        gridbar(gen);
        // P2: wtwh + target rowdot + zero inner states
        FOR_T(8, 16)
            tc_tile<1>(acc, bm, bn, 1024, g_HtH, g_HtL, g_CtH, g_CtL, g_WthH, g_WthL, sm);
            epi_store(acc, bm, bn, g_wtwh, 1024, 0);
        END_T
        for (int u = blockIdx.x; u < 32; u += NB) {
            int row = u * 8 + (tid >> 5), lane = tid & 31;
            const float* x = g_ht + ((size_t)row << 9);
            float s = 0.f;
#pragma unroll
            for (int k = lane * 4; k < 512; k += 128) {
                float4 xv = *(const float4*)(x + k);
                float4 wv = *(const float4*)(reg_w + k);
                s = fmaf(xv.x, wv.x, s); s = fmaf(xv.y, wv.y, s);
                s = fmaf(xv.z, wv.z, s); s = fmaf(xv.w, wv.w, s);
            }
#pragma unroll
            for (int o = 16; o; o >>= 1) s += __shfl_xor_sync(0xffffffffu, s, o);
            if (lane == 0) { s += reg_b[0]; out[row * LOOKN + t] = s; g_lab[row] = s; }
        }
        for (int i = gtid; i < 256 * 512; i += gs) {
            g_ce[i] = 0.f; g_cm[i] = 0.f;
            g_HeH[0][i] = z; g_HeL[0][i] = z;
            g_CeH[i] = z;    g_CeL[i] = z;
            g_HmH[0][i] = z; g_HmL[0][i] = z;
        }
        gridbar(gen);

        // ---- sp attention loop ----
#pragma unroll 1
        for (int l = 0; l < LE; l++) {
            const int cur = l & 1, nxt = cur ^ 1;
            // P3: u = tanh([he|ce]@We^T + wi_l + wt)
            FOR_T(8, 8)
                tc_tile<1>(acc, bm, bn, 1024, g_HeH[cur], g_HeL[cur], g_CeH, g_CeL,
                           g_WeH, g_WeL, sm);
                epi_u(acc, bm, bn, l);
            END_T
            gridbar(gen);
            // P4: score = u @ Vd^T + Vd_b
            FOR_T(8, 8)
                tc_tile<0>(acc, bm, bn, 512, g_UH, g_UL, 0, 0, g_VdH, g_VdL, sm);
                epi_store(acc, bm, bn, g_score, 512, Vd_b);
            END_T
            gridbar(gen);
            // P5: xmod = x * softmax(score), write splits
            for (int r = blockIdx.x; r < 256; r += NB) {
                __syncthreads();
                float v0 = g_score[(r << 9) + tid], v1 = g_score[(r << 9) + tid + 256];
                float mx = fmaxf(v0, v1);
#pragma unroll
                for (int o = 16; o; o >>= 1) mx = fmaxf(mx, __shfl_xor_sync(0xffffffffu, mx, o));
                if ((tid & 31) == 0) smf[tid >> 5] = mx;
                __syncthreads();
                float M = smf[0];
#pragma unroll
                for (int i = 1; i < 8; i++) M = fmaxf(M, smf[i]);
                float e0 = expf(v0 - M), e1 = expf(v1 - M);
                float sv = e0 + e1;
#pragma unroll
                for (int o = 16; o; o >>= 1) sv += __shfl_xor_sync(0xffffffffu, sv, o);
                __syncthreads();
                if ((tid & 31) == 0) smf[tid >> 5] = sv;
                __syncthreads();
                float S = 0.f;
#pragma unroll
                for (int i = 0; i < 8; i++) S += smf[i];
                float inv = 1.f / S;
                const float* xr = input + ((size_t)r * 48 + l) * 512;
                bsplit(xr[tid] * e0 * inv, g_XmH[(r << 9) + tid], g_XmL[(r << 9) + tid]);
                bsplit(xr[tid + 256] * e1 * inv, g_XmH[(r << 9) + tid + 256],
                       g_XmL[(r << 9) + tid + 256]);
            }
            gridbar(gen);
            // P6: sp gates + LSTM -> he(nxt), ce, mid[l]
            FOR_T(8, 32)
                tc_tile<1>(acc, bm, bn, 1024, g_XmH, g_XmL, g_HeH[cur], g_HeL[cur],
                           g_WspH, g_WspL, sm);
                epi_lstm(acc, bm, bn, g_bs, g_ce, 0, g_HeH[nxt], g_HeL[nxt],
                         g_CeH, g_CeL, 0, g_MidH, g_MidL, (size_t)l * 131072, 512);
            END_T
            gridbar(gen);
        }

        // ---- mid LSTM loop ----
#pragma unroll 1
        for (int l = 0; l < LE; l++) {
            const int cur = l & 1, nxt = cur ^ 1;
            FOR_T(8, 32)
                tc_tile<1>(acc, bm, bn, 1024, g_MidH + (size_t)l * 131072,
                           g_MidL + (size_t)l * 131072, g_HmH[cur], g_HmL[cur],
                           g_WmidH, g_WmidL, sm);
                epi_lstm(acc, bm, bn, g_bm, g_cm, 0, g_HmH[nxt], g_HmL[nxt],
                         0, 0, g_mid2, g_M2H, g_M2L, (size_t)l * 512, LE * 512);
            END_T
            gridbar(gen);
        }

        // P8: u2 = tanh(mid2 @ Wx^T + Wx_b + wh)
        FOR_T(384, 8)
            tc_tile<0>(acc, bm, bn, 512, g_M2H, g_M2L, 0, 0, g_WxH, g_WxL, sm);
            epi_u2(acc, bm, bn, Wx_b);
        END_T
        gridbar(gen);
        // P9: sc = u2 @ V_w + V_b
        for (int u = blockIdx.x; u < MM2 / 8; u += NB) {
            int row = u * 8 + (tid >> 5), lane = tid & 31;
            const float* x = g_u2 + ((size_t)row << 9);
            float s = 0.f;
#pragma unroll
            for (int k = lane * 4; k < 512; k += 128) {
                float4 xv = *(const float4*)(x + k);
                float4 wv = *(const float4*)(V_w + k);
                s = fmaf(xv.x, wv.x, s); s = fmaf(xv.y, wv.y, s);
                s = fmaf(xv.z, wv.z, s); s = fmaf(xv.w, wv.w, s);
            }
#pragma unroll
            for (int o = 16; o; o >>= 1) s += __shfl_xor_sync(0xffffffffu, s, o);
            if (lane == 0) g_sc[row] = s + V_b[0];
        }
        gridbar(gen);
        // P10: dec_in
        for (int b = blockIdx.x; b < 256; b += NB) {
            __syncthreads();
            if (tid < LE) smf[tid] = g_sc[b * LE + tid];
            __syncthreads();
            for (int h2 = tid; h2 < 512; h2 += NT) {
                float s = 0.f;
                const float* m2 = g_mid2 + (size_t)b * LE * 512 + h2;
#pragma unroll 8
                for (int ll = 0; ll < LE; ll++) s = fmaf(smf[ll], m2[(size_t)ll * 512], s);
                g_dec[(b << 9) + h2] = s;
            }
        }
        gridbar(gen);
    }
}

extern "C" void kernel_launch(void* const* d_in, const int* in_sizes, int n_in,
                              void* d_out, int out_size) {
    mega<<<NB, NT, 27648>>>(
        (const float*)d_in[0],  (const float*)d_in[1],  (const float*)d_in[2],
        (const float*)d_in[3],  (const float*)d_in[4],  (const float*)d_in[5],
        (const float*)d_in[6],  (const float*)d_in[7],  (const float*)d_in[8],
        (const float*)d_in[9],  (const float*)d_in[10], (const float*)d_in[11],
        (const float*)d_in[12], (const float*)d_in[13], (const float*)d_in[14],
        (const float*)d_in[15], (const float*)d_in[16], (const float*)d_in[17],
        (const float*)d_in[18], (const float*)d_in[19], (const float*)d_in[20],
        (const float*)d_in[21], (const float*)d_in[22], (const float*)d_in[23],
        (const float*)d_in[24], (const float*)d_in[25], (const float*)d_in[26],
        (float*)d_out);
}

// round 8
// speedup vs baseline: 2.8631x; 1.8899x over previous
#include <cuda_runtime.h>
#include <cuda_bf16.h>
#include <math.h>
typedef __nv_bfloat16 bf;
#define NB 148
#define NT 256
#define LOOKN 10
#define LE 48
#define MM2 12288
#define KTG 1088

// ---------------- device scratch ----------------
__device__ bf g_WtgH[2048*KTG], g_WtgL[2048*KTG];
__device__ bf g_WspH[2048*1024], g_WspL[2048*1024];
__device__ bf g_WmidH[2048*1024], g_WmidL[2048*1024];
__device__ bf g_WthH[1024*1024], g_WthL[1024*1024];
__device__ bf g_WeH[512*1024], g_WeL[512*1024];
__device__ bf g_VdH[512*512], g_VdL[512*512];
__device__ bf g_WxH[512*512], g_WxL[512*512];
__device__ bf g_WiH[512*512], g_WiL[512*512];
__device__ bf g_InH[MM2*512], g_InL[MM2*512];
__device__ bf g_AtgH[256*KTG], g_AtgL[256*KTG];
__device__ bf g_HtH[256*512], g_HtL[256*512];
__device__ bf g_CtH[256*512], g_CtL[256*512];
__device__ bf g_HeH[2][256*512], g_HeL[2][256*512];
__device__ bf g_CeH[256*512], g_CeL[256*512];
__device__ bf g_HmH[2][256*512], g_HmL[2][256*512];
__device__ bf g_XmH[256*512], g_XmL[256*512];
__device__ bf g_UH[256*512], g_UL[256*512];
__device__ bf g_MidH[LE*256*512], g_MidL[LE*256*512];
__device__ bf g_M2H[MM2*512], g_M2L[MM2*512];
__device__ float g_bt[2048], g_bs[2048], g_bm[2048];
__device__ float g_wi[MM2*512], g_mid2[MM2*512], g_u2[MM2*512];
__device__ float g_ht[256*512], g_ct[256*512], g_ce[256*512], g_cm[256*512];
__device__ float g_dec[256*512], g_wtwh[256*1024], g_score[256*512];
__device__ float g_lab[256], g_sc[MM2];
__device__ unsigned g_bc, g_bg;

__device__ __forceinline__ void gridbar(unsigned &gen) {
    __syncthreads();
    if (threadIdx.x == 0) {
        __threadfence();
        if (atomicAdd(&g_bc, 1u) == (unsigned)(NB - 1)) {
            g_bc = 0u; __threadfence();
            atomicExch(&g_bg, gen + 1u);
        } else {
            while (*((volatile unsigned*)&g_bg) == gen) __nanosleep(32);
        }
        __threadfence();
    }
    __syncthreads();
    gen++;
}
__device__ __forceinline__ float sigm(float x) { return 1.f / (1.f + expf(-x)); }
__device__ __forceinline__ void bsplit(float x, bf &h, bf &l) {
    h = __float2bfloat16(x);
    l = __float2bfloat16(x - __bfloat162float(h));
}
__device__ __forceinline__ unsigned su32(const void* p) {
    return (unsigned)__cvta_generic_to_shared(p);
}
__device__ __forceinline__ void ldsm4(unsigned a, unsigned* r) {
    asm volatile("ldmatrix.sync.aligned.m8n8.x4.shared.b16 {%0,%1,%2,%3}, [%4];"
                 : "=r"(r[0]), "=r"(r[1]), "=r"(r[2]), "=r"(r[3]) : "r"(a));
}
__device__ __forceinline__ void mma16816(float* d, const unsigned* a, const unsigned* b) {
    asm volatile("mma.sync.aligned.m16n8k16.row.col.f32.bf16.bf16.f32 "
                 "{%0,%1,%2,%3}, {%4,%5,%6,%7}, {%8,%9}, {%0,%1,%2,%3};"
                 : "+f"(d[0]), "+f"(d[1]), "+f"(d[2]), "+f"(d[3])
                 : "r"(a[0]), "r"(a[1]), "r"(a[2]), "r"(a[3]), "r"(b[0]), "r"(b[1]));
}
__device__ __forceinline__ void cpa16(unsigned d, const void* s) {
    asm volatile("cp.async.cg.shared.global [%0], [%1], 16;" :: "r"(d), "l"(s));
}
__device__ __forceinline__ void cpcommit() { asm volatile("cp.async.commit_group;"); }
template<int N> __device__ __forceinline__ void cpwait() {
    asm volatile("cp.async.wait_group %0;" :: "n"(N));
}

// -------- TC tile engine: (MI*32)m x 64n, 8 warps (2m x 4n), split-bf16 3-pass,
// cp.async double-buffered K-staging (64 per stage). CAT2: A=[seg0|seg1] each ld 512.
template <int MI, int CAT2>
__device__ void tc_tile(float acc[][2][4], int bm, int bn, int K,
                        const bf* __restrict__ A0h, const bf* __restrict__ A0l,
                        const bf* __restrict__ A1h, const bf* __restrict__ A1l,
                        const bf* __restrict__ Bh, const bf* __restrict__ Bl, char* sm) {
    const int TM = MI * 32;
    const unsigned BUF = (unsigned)(2 * TM + 128) * 144;
    const int tid = threadIdx.x, lane = tid & 31, w = tid >> 5;
    const unsigned sb = su32(sm);
#pragma unroll
    for (int mi = 0; mi < MI; mi++)
#pragma unroll
        for (int nf = 0; nf < 2; nf++)
#pragma unroll
            for (int k = 0; k < 4; k++) acc[mi][nf][k] = 0.f;
    const int ns = K >> 6;
    auto stage = [&](int st) {
        unsigned base = sb + (st & 1) * BUF;
        int k0 = st << 6;
#pragma unroll
        for (int c = tid; c < TM * 16; c += NT) {
            int p = c >= TM * 8 ? 1 : 0;
            int cc = c - p * TM * 8;
            int row = cc >> 3, q = cc & 7;
            int gk = k0 + q * 8;
            const bf* src;
            if (CAT2) src = (gk < 512) ? ((p ? A0l : A0h) + (size_t)(bm + row) * 512 + gk)
                                       : ((p ? A1l : A1h) + (size_t)(bm + row) * 512 + gk - 512);
            else      src = (p ? A0l : A0h) + (size_t)(bm + row) * K + gk;
            cpa16(base + (unsigned)(p * TM + row) * 144 + q * 16, src);
        }
        unsigned bb = base + (unsigned)(2 * TM) * 144;
#pragma unroll
        for (int c = tid; c < 1024; c += NT) {
            int p = c >> 9, row = (c >> 3) & 63, q = c & 7;
            cpa16(bb + (unsigned)(p * 64 + row) * 144 + q * 16,
                  (p ? Bl : Bh) + (size_t)(bn + row) * K + k0 + q * 8);
        }
        cpcommit();
    };
    stage(0);
    const unsigned offA = (unsigned)((w & 1) * (MI * 16) + (lane & 15)) * 144 + (lane >> 4) * 16;
    const unsigned offB = (unsigned)(2 * TM) * 144
                        + (unsigned)((w >> 1) * 16 + ((lane >> 4) << 3) + (lane & 7)) * 144
                        + ((lane >> 3) & 1) * 16;
    for (int st = 0; st < ns; st++) {
        if (st + 1 < ns) { stage(st + 1); cpwait<1>(); }
        else cpwait<0>();
        __syncthreads();
        unsigned base = sb + (st & 1) * BUF;
#pragma unroll
        for (int kk = 0; kk < 4; kk++) {
            unsigned aH[MI][4], aL[MI][4], bH[4], bL[4];
#pragma unroll
            for (int mi = 0; mi < MI; mi++) {
                ldsm4(base + offA + (unsigned)(mi * 16) * 144 + kk * 32, aH[mi]);
                ldsm4(base + offA + (unsigned)(TM + mi * 16) * 144 + kk * 32, aL[mi]);
            }
            ldsm4(base + offB + kk * 32, bH);
            ldsm4(base + offB + (unsigned)64 * 144 + kk * 32, bL);
#pragma unroll
            for (int mi = 0; mi < MI; mi++)
#pragma unroll
                for (int nf = 0; nf < 2; nf++) {
                    mma16816(acc[mi][nf], aH[mi], bH + 2 * nf);
                    mma16816(acc[mi][nf], aH[mi], bL + 2 * nf);
                    mma16816(acc[mi][nf], aL[mi], bH + 2 * nf);
                }
        }
        __syncthreads();
    }
}

// ---------------- epilogues ----------------
template <int MI>
__device__ void epi_store(float acc[][2][4], int bm, int bn, float* C, int ldc,
                          const float* bias) {
    int lane = threadIdx.x & 31, w = threadIdx.x >> 5;
    int wm = (w & 1) * (MI * 16), wn = (w >> 1) * 16;
#pragma unroll
    for (int mi = 0; mi < MI; mi++)
#pragma unroll
        for (int nf = 0; nf < 2; nf++)
#pragma unroll
            for (int k = 0; k < 4; k++) {
                int m = bm + wm + mi * 16 + (lane >> 2) + (k >> 1) * 8;
                int nc = bn + wn + nf * 8 + (lane & 3) * 2 + (k & 1);
                float v = acc[mi][nf][k];
                if (bias) v += bias[nc];
                C[(size_t)m * ldc + nc] = v;
            }
}
template <int MI>
__device__ void epi_u(float acc[][2][4], int bm, int bn, int l) {
    int lane = threadIdx.x & 31, w = threadIdx.x >> 5;
    int wm = (w & 1) * (MI * 16), wn = (w >> 1) * 16;
#pragma unroll
    for (int mi = 0; mi < MI; mi++)
#pragma unroll
        for (int nf = 0; nf < 2; nf++)
#pragma unroll
            for (int k = 0; k < 4; k++) {
                int m = bm + wm + mi * 16 + (lane >> 2) + (k >> 1) * 8;
                int nc = bn + wn + nf * 8 + (lane & 3) * 2 + (k & 1);
                float v = tanhf(acc[mi][nf][k] + g_wi[((size_t)m * 48 + l) * 512 + nc]
                                + g_wtwh[(size_t)m * 1024 + nc]);
                size_t ix = ((size_t)m << 9) + nc;
                bsplit(v, g_UH[ix], g_UL[ix]);
            }
}
template <int MI>
__device__ void epi_u2(float acc[][2][4], int bm, int bn, const float* wxb) {
    int lane = threadIdx.x & 31, w = threadIdx.x >> 5;
    int wm = (w & 1) * (MI * 16), wn = (w >> 1) * 16;
#pragma unroll
    for (int mi = 0; mi < MI; mi++)
#pragma unroll
        for (int nf = 0; nf < 2; nf++)
#pragma unroll
            for (int k = 0; k < 4; k++) {
                int m = bm + wm + mi * 16 + (lane >> 2) + (k >> 1) * 8;
                int nc = bn + wn + nf * 8 + (lane & 3) * 2 + (k & 1);
                float v = tanhf(acc[mi][nf][k] + wxb[nc]
                                + g_wtwh[(size_t)(m / 48) * 1024 + 512 + nc]);
                g_u2[(size_t)m * 512 + nc] = v;
            }
}
// interleaved-gate LSTM epilogue (B rows packed n' = j*4 + gate)
template <int MI>
__device__ void epi_lstm(float acc[][2][4], int bm, int bn, const float* bias,
                         float* cP, float* hF, bf* hH, bf* hL, bf* cH, bf* cL,
                         float* eF, bf* eH, bf* eL, size_t eOff, int eStr) {
    int lane = threadIdx.x & 31, w = threadIdx.x >> 5;
    int wm = (w & 1) * (MI * 16), wn = (w >> 1) * 16;
    int q = lane & 3;
#pragma unroll
    for (int mi = 0; mi < MI; mi++)
#pragma unroll
        for (int nf = 0; nf < 2; nf++)
#pragma unroll
            for (int rh = 0; rh < 2; rh++) {
                float va = acc[mi][nf][rh * 2 + 0], vb = acc[mi][nf][rh * 2 + 1];
                float pa = __shfl_xor_sync(0xffffffffu, va, 1);
                float pb = __shfl_xor_sync(0xffffffffu, vb, 1);
                if (!(q & 1)) {
                    int m = bm + wm + mi * 16 + (lane >> 2) + rh * 8;
                    int j = (bn + wn + nf * 8 + q * 2) >> 2;
                    float gi = va + bias[j], gf = vb + bias[512 + j];
                    float gg = pa + bias[1024 + j], go = pb + bias[1536 + j];
                    size_t ix = ((size_t)m << 9) + j;
                    float c2 = sigm(gf) * cP[ix] + sigm(gi) * tanhf(gg);
                    float hn = sigm(go) * tanhf(c2);
                    cP[ix] = c2;
                    bf hh, hl; bsplit(hn, hh, hl);
                    hH[ix] = hh; hL[ix] = hl;
                    if (hF) hF[ix] = hn;
                    if (cH) { bf ch, cl; bsplit(c2, ch, cl); cH[ix] = ch; cL[ix] = cl; }
                    if (eH) {
                        size_t ex = (size_t)m * eStr + eOff + j;
                        eH[ex] = hh; eL[ex] = hl;
                        if (eF) eF[ex] = hn;
                    }
                }
            }
}

// ---------------- megakernel ----------------
__global__ void __launch_bounds__(NT, 1)
mega(const float* __restrict__ input, const float* __restrict__ label_p,
     const float* __restrict__ Wih_sp, const float* __restrict__ Whh_sp,
     const float* __restrict__ bih_sp, const float* __restrict__ bhh_sp,
     const float* __restrict__ Wih_tg, const float* __restrict__ Whh_tg,
     const float* __restrict__ bih_tg, const float* __restrict__ bhh_tg,
     const float* __restrict__ Wih_mid, const float* __restrict__ Whh_mid,
     const float* __restrict__ bih_mid, const float* __restrict__ bhh_mid,
     const float* __restrict__ Wi_w, const float* __restrict__ Wi_b,
     const float* __restrict__ We_w, const float* __restrict__ Wt_w,
     const float* __restrict__ Vd_w, const float* __restrict__ Vd_b,
     const float* __restrict__ Wx_w, const float* __restrict__ Wx_b,
     const float* __restrict__ Wh_w, const float* __restrict__ V_w,
     const float* __restrict__ V_b, const float* __restrict__ reg_w,
     const float* __restrict__ reg_b, float* __restrict__ out) {
    extern __shared__ char sm[];
    float* smf = (float*)sm;
    unsigned gen = *((volatile unsigned*)&g_bg);
    const int tid = threadIdx.x;
    const int gtid = blockIdx.x * NT + tid;
    const int gs = NB * NT;
    const bf z = __float2bfloat16(0.f);

    // ---- S0: split/pack weights, biases, init ----
    for (int i = gtid; i < 2048 * KTG; i += gs) {
        int np = i / KTG, cc = i - np * KTG;
        int r = (np & 3) * 512 + (np >> 2);
        float v = 0.f;
        if (cc < 513)       v = Wih_tg[r * 513 + cc];
        else if (cc < 1025) v = Whh_tg[(r << 9) + cc - 513];
        bsplit(v, g_WtgH[i], g_WtgL[i]);
    }
    for (int i = gtid; i < 2048 * 1024; i += gs) {
        int np = i >> 10, cc = i & 1023;
        int r = (np & 3) * 512 + (np >> 2);
        float vs = cc < 512 ? Wih_sp[(r << 9) + cc] : Whh_sp[(r << 9) + cc - 512];
        float vm = cc < 512 ? Wih_mid[(r << 9) + cc] : Whh_mid[(r << 9) + cc - 512];
        bsplit(vs, g_WspH[i], g_WspL[i]);
        bsplit(vm, g_WmidH[i], g_WmidL[i]);
    }
    for (int i = gtid; i < 1024 * 1024; i += gs) {
        int r = i >> 10, cc = i & 1023;
        float v = r < 512 ? Wt_w[(r << 10) + cc] : Wh_w[((r - 512) << 10) + cc];
        bsplit(v, g_WthH[i], g_WthL[i]);
    }
    for (int i = gtid; i < 512 * 1024; i += gs) bsplit(We_w[i], g_WeH[i], g_WeL[i]);
    for (int i = gtid; i < 512 * 512; i += gs) {
        bsplit(Vd_w[i], g_VdH[i], g_VdL[i]);
        bsplit(Wx_w[i], g_WxH[i], g_WxL[i]);
        bsplit(Wi_w[i], g_WiH[i], g_WiL[i]);
    }
    for (int i = gtid; i < MM2 * 512; i += gs) bsplit(input[i], g_InH[i], g_InL[i]);
    for (int i = gtid; i < 2048; i += gs) {
        g_bt[i] = bih_tg[i] + bhh_tg[i];
        g_bs[i] = bih_sp[i] + bhh_sp[i];
        g_bm[i] = bih_mid[i] + bhh_mid[i];
    }
    for (int i = gtid; i < 256 * 512; i += gs) { g_ht[i] = 0.f; g_ct[i] = 0.f; g_dec[i] = 0.f; }
    for (int i = gtid; i < 256; i += gs) g_lab[i] = label_p[i * (LE + LOOKN) + LE];
    gridbar(gen);

    // ---- S1: wi = input @ Wi^T + Wi_b (12288x512x512), MI=2 ----
    for (int _t = blockIdx.x; _t < 1536; _t += NB) {
        int bm = (_t >> 3) * 64, bn = (_t & 7) * 64;
        float acc[2][2][4];
        tc_tile<2, 0>(acc, bm, bn, 512, g_InH, g_InL, 0, 0, g_WiH, g_WiL, sm);
        epi_store<2>(acc, bm, bn, g_wi, 512, Wi_b);
    }
    gridbar(gen);

#pragma unroll 1
    for (int t = 0; t < LOOKN; t++) {
        // PA: pack Atg (split)
        for (int i = gtid; i < 256 * KTG; i += gs) {
            int b = i / KTG, c = i - b * KTG;
            float v = 0.f;
            if (c == 0)        v = g_lab[b];
            else if (c < 513)  v = g_dec[(b << 9) + c - 1];
            else if (c < 1025) v = g_ht[(b << 9) + c - 513];
            bsplit(v, g_AtgH[i], g_AtgL[i]);
        }
        gridbar(gen);
        // P1: tg gates + LSTM (MI=2, 128 tiles)
        for (int _t = blockIdx.x; _t < 128; _t += NB) {
            int bm = (_t >> 5) * 64, bn = (_t & 31) * 64;
            float acc[2][2][4];
            tc_tile<2, 0>(acc, bm, bn, KTG, g_AtgH, g_AtgL, 0, 0, g_WtgH, g_WtgL, sm);
            epi_lstm<2>(acc, bm, bn, g_bt, g_ct, g_ht, g_HtH, g_HtL, g_CtH, g_CtL,
                        0, 0, 0, 0, 0);
        }
        gridbar(gen);
        // P2: wtwh (MI=1, 128 tiles) + target rowdot + zero inner states
        for (int _t = blockIdx.x; _t < 128; _t += NB) {
            int bm = (_t >> 4) * 32, bn = (_t & 15) * 64;
            float acc[1][2][4];
            tc_tile<1, 1>(acc, bm, bn, 1024, g_HtH, g_HtL, g_CtH, g_CtL, g_WthH, g_WthL, sm);
            epi_store<1>(acc, bm, bn, g_wtwh, 1024, 0);
        }
        for (int u = blockIdx.x; u < 32; u += NB) {
            int row = u * 8 + (tid >> 5), lane = tid & 31;
            const float* x = g_ht + ((size_t)row << 9);
            float s = 0.f;
#pragma unroll
            for (int k = lane * 4; k < 512; k += 128) {
                float4 xv = *(const float4*)(x + k);
                float4 wv = *(const float4*)(reg_w + k);
                s = fmaf(xv.x, wv.x, s); s = fmaf(xv.y, wv.y, s);
                s = fmaf(xv.z, wv.z, s); s = fmaf(xv.w, wv.w, s);
            }
#pragma unroll
            for (int o = 16; o; o >>= 1) s += __shfl_xor_sync(0xffffffffu, s, o);
            if (lane == 0) { s += reg_b[0]; out[row * LOOKN + t] = s; g_lab[row] = s; }
        }
        for (int i = gtid; i < 256 * 512; i += gs) {
            g_ce[i] = 0.f; g_cm[i] = 0.f;
            g_HeH[0][i] = z; g_HeL[0][i] = z;
            g_CeH[i] = z;    g_CeL[i] = z;
            g_HmH[0][i] = z; g_HmL[0][i] = z;
        }
        gridbar(gen);

        // ---- sp attention loop ----
#pragma unroll 1
        for (int l = 0; l < LE; l++) {
            const int cur = l & 1, nxt = cur ^ 1;
            // P3: u = tanh([he|ce]@We^T + wi_l + wt) (MI=1, 64 tiles)
            for (int _t = blockIdx.x; _t < 64; _t += NB) {
                int bm = (_t >> 3) * 32, bn = (_t & 7) * 64;
                float acc[1][2][4];
                tc_tile<1, 1>(acc, bm, bn, 1024, g_HeH[cur], g_HeL[cur], g_CeH, g_CeL,
                              g_WeH, g_WeL, sm);
                epi_u<1>(acc, bm, bn, l);
            }
            gridbar(gen);
            // P4: score = u @ Vd^T + Vd_b (MI=1, 64 tiles)
            for (int _t = blockIdx.x; _t < 64; _t += NB) {
                int bm = (_t >> 3) * 32, bn = (_t & 7) * 64;
                float acc[1][2][4];
                tc_tile<1, 0>(acc, bm, bn, 512, g_UH, g_UL, 0, 0, g_VdH, g_VdL, sm);
                epi_store<1>(acc, bm, bn, g_score, 512, Vd_b);
            }
            gridbar(gen);
            // P5: xmod = x * softmax(score)
            for (int r = blockIdx.x; r < 256; r += NB) {
                __syncthreads();
                float v0 = g_score[(r << 9) + tid], v1 = g_score[(r << 9) + tid + 256];
                float mx = fmaxf(v0, v1);
#pragma unroll
                for (int o = 16; o; o >>= 1) mx = fmaxf(mx, __shfl_xor_sync(0xffffffffu, mx, o));
                if ((tid & 31) == 0) smf[tid >> 5] = mx;
                __syncthreads();
                float M = smf[0];
#pragma unroll
                for (int i = 1; i < 8; i++) M = fmaxf(M, smf[i]);
                float e0 = expf(v0 - M), e1 = expf(v1 - M);
                float sv = e0 + e1;
#pragma unroll
                for (int o = 16; o; o >>= 1) sv += __shfl_xor_sync(0xffffffffu, sv, o);
                __syncthreads();
                if ((tid & 31) == 0) smf[tid >> 5] = sv;
                __syncthreads();
                float S = 0.f;
#pragma unroll
                for (int i = 0; i < 8; i++) S += smf[i];
                float inv = 1.f / S;
                const float* xr = input + ((size_t)r * 48 + l) * 512;
                bsplit(xr[tid] * e0 * inv, g_XmH[(r << 9) + tid], g_XmL[(r << 9) + tid]);
                bsplit(xr[tid + 256] * e1 * inv, g_XmH[(r << 9) + tid + 256],
                       g_XmL[(r << 9) + tid + 256]);
            }
            gridbar(gen);
            // P6: sp gates + LSTM (MI=2, 128 tiles)
            for (int _t = blockIdx.x; _t < 128; _t += NB) {
                int bm = (_t >> 5) * 64, bn = (_t & 31) * 64;
                float acc[2][2][4];
                tc_tile<2, 1>(acc, bm, bn, 1024, g_XmH, g_XmL, g_HeH[cur], g_HeL[cur],
                              g_WspH, g_WspL, sm);
                epi_lstm<2>(acc, bm, bn, g_bs, g_ce, 0, g_HeH[nxt], g_HeL[nxt],
                            g_CeH, g_CeL, 0, g_MidH, g_MidL, (size_t)l * 131072, 512);
            }
            gridbar(gen);
        }

        // ---- mid LSTM loop ----
#pragma unroll 1
        for (int l = 0; l < LE; l++) {
            const int cur = l & 1, nxt = cur ^ 1;
            for (int _t = blockIdx.x; _t < 128; _t += NB) {
                int bm = (_t >> 5) * 64, bn = (_t & 31) * 64;
                float acc[2][2][4];
                tc_tile<2, 1>(acc, bm, bn, 1024, g_MidH + (size_t)l * 131072,
                              g_MidL + (size_t)l * 131072, g_HmH[cur], g_HmL[cur],
                              g_WmidH, g_WmidL, sm);
                epi_lstm<2>(acc, bm, bn, g_bm, g_cm, 0, g_HmH[nxt], g_HmL[nxt],
                            0, 0, g_mid2, g_M2H, g_M2L, (size_t)l * 512, LE * 512);
            }
            gridbar(gen);
        }

        // P8: u2 = tanh(mid2 @ Wx^T + Wx_b + wh) (MI=2, 1536 tiles)
        for (int _t = blockIdx.x; _t < 1536; _t += NB) {
            int bm = (_t >> 3) * 64, bn = (_t & 7) * 64;
            float acc[2][2][4];
            tc_tile<2, 0>(acc, bm, bn, 512, g_M2H, g_M2L, 0, 0, g_WxH, g_WxL, sm);
            epi_u2<2>(acc, bm, bn, Wx_b);
        }
        gridbar(gen);
        // P9: sc = u2 @ V_w + V_b
        for (int u = blockIdx.x; u < MM2 / 8; u += NB) {
            int row = u * 8 + (tid >> 5), lane = tid & 31;
            const float* x = g_u2 + ((size_t)row << 9);
            float s = 0.f;
#pragma unroll
            for (int k = lane * 4; k < 512; k += 128) {
                float4 xv = *(const float4*)(x + k);
                float4 wv = *(const float4*)(V_w + k);
                s = fmaf(xv.x, wv.x, s); s = fmaf(xv.y, wv.y, s);
                s = fmaf(xv.z, wv.z, s); s = fmaf(xv.w, wv.w, s);
            }
#pragma unroll
            for (int o = 16; o; o >>= 1) s += __shfl_xor_sync(0xffffffffu, s, o);
            if (lane == 0) g_sc[row] = s + V_b[0];
        }
        gridbar(gen);
        // P10: dec_in
        for (int b = blockIdx.x; b < 256; b += NB) {
            __syncthreads();
            if (tid < LE) smf[tid] = g_sc[b * LE + tid];
            __syncthreads();
            for (int h2 = tid; h2 < 512; h2 += NT) {
                float s = 0.f;
                const float* m2 = g_mid2 + (size_t)b * LE * 512 + h2;
#pragma unroll 8
                for (int ll = 0; ll < LE; ll++) s = fmaf(smf[ll], m2[(size_t)ll * 512], s);
                g_dec[(b << 9) + h2] = s;
            }
        }
        gridbar(gen);
    }
}

extern "C" void kernel_launch(void* const* d_in, const int* in_sizes, int n_in,
                              void* d_out, int out_size) {
    cudaFuncSetAttribute(mega, cudaFuncAttributeMaxDynamicSharedMemorySize, 73728);
    mega<<<NB, NT, 73728>>>(
        (const float*)d_in[0],  (const float*)d_in[1],  (const float*)d_in[2],
        (const float*)d_in[3],  (const float*)d_in[4],  (const float*)d_in[5],
        (const float*)d_in[6],  (const float*)d_in[7],  (const float*)d_in[8],
        (const float*)d_in[9],  (const float*)d_in[10], (const float*)d_in[11],
        (const float*)d_in[12], (const float*)d_in[13], (const float*)d_in[14],
        (const float*)d_in[15], (const float*)d_in[16], (const float*)d_in[17],
        (const float*)d_in[18], (const float*)d_in[19], (const float*)d_in[20],
        (const float*)d_in[21], (const float*)d_in[22], (const float*)d_in[23],
        (const float*)d_in[24], (const float*)d_in[25], (const float*)d_in[26],
        (float*)d_out);
}